// round 9
// baseline (speedup 1.0000x reference)
#include <cuda_runtime.h>
#include <cuda_bf16.h>
#include <cstdint>
#include <math.h>

#define TAU 0.5f
#define B 16
#define H 96
#define W 96
#define NPIX (H * W)
#define NMASK 32          // 16 pred masks + 16 label masks; block b builds mask b
#define NT 768            // 24 warps
#define NWRP (NT / 32)
#define NWORDS 288        // 96 rows x 3 words
#define BIG 100000

// static device scratch (no allocation)
__device__ uint32_t g_words[NMASK * NWORDS];
__device__ int g_maxAB[B], g_maxBA[B];
__device__ int g_anyP[B], g_anyL[B];
__device__ int g_ready = 0;
__device__ int g_done2 = 0;

// exact search over padded target bitmask for one pixel (rare / far path)
__device__ __noinline__ int full_search(const uint32_t* mtp, int x, int y)
{
    int best = BIG;
    for (int yy = 0; yy < H; yy++) {
        int dy2 = (yy - y) * (yy - y);
        if (dy2 >= best) continue;
        #pragma unroll
        for (int w = 0; w < 3; w++) {
            uint32_t m = mtp[(yy + 2) * 5 + 1 + w];
            while (m) {
                int bp = __ffs(m) - 1; m &= m - 1;
                int dx = w * 32 + bp - x;
                best = min(best, dy2 + dx * dx);
            }
        }
    }
    return best;
}

__global__ void __launch_bounds__(NT, 1)
hd_all(const float* __restrict__ pred,
       const float* __restrict__ tgt,
       float* __restrict__ out)
{
    __shared__ uint32_t mtp[(H + 4) * 5];   // padded target mask
    __shared__ uint32_t sq[NWORDS];         // own (query) mask words
    __shared__ int s_red[NWRP], s_any[NWRP];
    __shared__ int s_last;

    const int bx   = blockIdx.x;            // mask id == job id
    const int tid  = threadIdx.x;
    const int lane = tid & 31;
    const int wrp  = tid >> 5;
    const int img  = bx & 15;
    const int dir  = bx >> 4;               // 0: q=pred,t=label ; 1: reverse

    const float4* src = (const float4*)((bx < B) ? (pred + bx * NPIX)
                                                 : (tgt + (bx - B) * NPIX));

    if (tid < (H + 4) * 5) mtp[tid] = 0u;   // zero incl. pads; interior overwritten

    // ---- phase A: build OWN mask only (3 x float4 -> nibble -> shfl-or) ----
    uint32_t* gw = g_words + bx * NWORDS;
    #pragma unroll
    for (int k = 0; k < 3; k++) {
        int i4 = tid + k * NT;
        float4 v = src[i4];
        uint32_t nib = (v.x >= TAU ? 1u : 0u) | (v.y >= TAU ? 2u : 0u)
                     | (v.z >= TAU ? 4u : 0u) | (v.w >= TAU ? 8u : 0u);
        uint32_t wv = nib << ((i4 & 7) * 4);
        wv |= __shfl_xor_sync(0xFFFFFFFFu, wv, 1);
        wv |= __shfl_xor_sync(0xFFFFFFFFu, wv, 2);
        wv |= __shfl_xor_sync(0xFFFFFFFFu, wv, 4);
        if ((lane & 7) == 0) {
            int w = i4 >> 3;
            gw[w] = wv;
            sq[w] = wv;
        }
    }

    // ---- publish + join: all 32 masks must be in L2 before phase B ----
    __threadfence();
    __syncthreads();
    if (tid == 0) {
        atomicAdd(&g_ready, 1);
        while (*(volatile int*)&g_ready != 0 &&
               *(volatile int*)&g_ready < NMASK)
            __nanosleep(32);
        __threadfence();
    }
    __syncthreads();

    // ---- stage target mask into padded smem ----
    if (tid < NWORDS) {
        uint32_t tw = g_words[(bx ^ B) * NWORDS + tid];
        int y = tid / 3, xw = tid - y * 3;
        mtp[(y + 2) * 5 + 1 + xw] = tw;
    }
    __syncthreads();

    // ---- phase B: bitwise 5x5 dilation, one word (32 px) per thread ----
    int pmax = 0, tany = 0;
    if (tid < NWORDS) {
        const int y  = tid / 3;
        const int wc = tid - y * 3;
        uint32_t C[5], h1[5], h2[5];
        #pragma unroll
        for (int j = 0; j < 5; j++) {
            uint32_t l = mtp[(y + j) * 5 + wc];
            uint32_t c = mtp[(y + j) * 5 + wc + 1];
            uint32_t r = mtp[(y + j) * 5 + wc + 2];
            C[j]  = c;
            h1[j] = __funnelshift_l(l, c, 1) | __funnelshift_r(c, r, 1);
            h2[j] = __funnelshift_l(l, c, 2) | __funnelshift_r(c, r, 2);
        }
        uint32_t D0 = C[2];
        uint32_t D1 = D0 | h1[2] | C[1] | C[3];
        uint32_t D2 = D1 | h1[1] | h1[3];
        uint32_t D4 = D2 | h2[2] | C[0] | C[4];
        uint32_t D5 = D4 | h2[1] | h2[3] | h1[0] | h1[4];
        uint32_t D8 = D5 | h2[0] | h2[4];

        uint32_t q = sq[tid];
        tany = (D0 != 0u);
        pmax = (q & ~D5) ? 8 : (q & ~D4) ? 5 : (q & ~D2) ? 4
             : (q & ~D1) ? 2 : (q & ~D0) ? 1 : 0;

        uint32_t fb = q & ~D8;              // d2 >= 9: exact fallback (~never)
        while (fb) {
            int bp = __ffs(fb) - 1; fb &= fb - 1;
            pmax = max(pmax, full_search(mtp, wc * 32 + bp, y));
        }
    }

    // ---- block reduction (max d2, target-any) ----
    #pragma unroll
    for (int o = 16; o > 0; o >>= 1) {
        pmax = max(pmax, __shfl_xor_sync(0xFFFFFFFFu, pmax, o));
        tany |= __shfl_xor_sync(0xFFFFFFFFu, tany, o);
    }
    if (lane == 0) { s_red[wrp] = pmax; s_any[wrp] = tany; }
    __syncthreads();
    if (tid < 32) {
        int v = (tid < NWRP) ? s_red[tid] : 0;
        int a = (tid < NWRP) ? s_any[tid] : 0;
        #pragma unroll
        for (int o = 16; o > 0; o >>= 1) {
            v = max(v, __shfl_xor_sync(0xFFFFFFFFu, v, o));
            a |= __shfl_xor_sync(0xFFFFFFFFu, a, o);
        }
        if (tid == 0) {
            if (dir == 0) { g_maxAB[img] = v; g_anyL[img] = a; }
            else          { g_maxBA[img] = v; g_anyP[img] = a; }
            __threadfence();
            int old = atomicAdd(&g_done2, 1);
            s_last = (old == NMASK - 1);
        }
    }
    __syncthreads();
    if (!s_last) return;
    __threadfence();

    // ---------------- finalize (exactly one block) ----------------
    __shared__ float hd[B];
    __shared__ int needs[B];    // 0 normal, 1 diam(pred), 2 diam(label)
    if (tid < B) {
        int aa = g_anyP[tid], bb = g_anyL[tid];
        if (aa && bb) {
            hd[tid] = sqrtf((float)max(g_maxAB[tid], g_maxBA[tid]));
            needs[tid] = 0;
        } else if (!aa && !bb) {
            hd[tid] = 0.0f;
            needs[tid] = 0;
        } else {
            needs[tid] = aa ? 1 : 2;
        }
    }
    if (tid == 0) { g_ready = 0; g_done2 = 0; }   // reset for next graph replay
    __syncthreads();

    // empty-set fallback: diameter (formal correctness; never runs on this data)
    __shared__ int s_diam;
    for (int im = 0; im < B; im++) {
        if (needs[im]) {
            const float* src2 = (needs[im] == 1) ? (pred + im * NPIX)
                                                 : (tgt  + im * NPIX);
            if (tid == 0) s_diam = 0;
            __syncthreads();
            int best = 0;
            for (int p = tid; p < NPIX; p += NT) {
                if (src2[p] >= TAU) {
                    int py = p / W, px = p - (p / W) * W;
                    for (int qq = 0; qq < NPIX; qq++) {
                        if (src2[qq] >= TAU) {
                            int dy = py - qq / W;
                            int dxx = px - (qq - (qq / W) * W);
                            best = max(best, dy * dy + dxx * dxx);
                        }
                    }
                }
            }
            atomicMax(&s_diam, best);
            __syncthreads();
            if (tid == 0) hd[im] = sqrtf((float)s_diam);
            __syncthreads();
        }
    }

    if (tid == 0) {
        float s = 0.0f;
        #pragma unroll
        for (int i = 0; i < B; i++) s += hd[i];
        out[0] = s * (1.0f / B);
    }
}

// ---------------------------------------------------------------------------
extern "C" void kernel_launch(void* const* d_in, const int* in_sizes, int n_in,
                              void* d_out, int out_size)
{
    const float* pred = (const float*)d_in[0];
    const float* tgt  = (const float*)d_in[1];
    float* out = (float*)d_out;

    hd_all<<<NMASK, NT>>>(pred, tgt, out);
}

// round 10
// speedup vs baseline: 1.0423x; 1.0423x over previous
#include <cuda_runtime.h>
#include <cuda_bf16.h>
#include <cstdint>
#include <math.h>

#define TAU 0.5f
#define B 16
#define H 96
#define W 96
#define NPIX (H * W)
#define NB (2 * B)        // 32 blocks: (image, direction)
#define NT 768            // 24 warps
#define NWRP (NT / 32)
#define NWORDS 288        // 96 rows x 3 words
#define BIG 100000

// static device scratch (no allocation)
__device__ int g_maxAB[B], g_maxBA[B];
__device__ int g_anyP[B], g_anyL[B];
__device__ int g_done = 0;

// exact search over padded target bitmask for one pixel (rare / far path)
__device__ __noinline__ int full_search(const uint32_t* mtp, int x, int y)
{
    int best = BIG;
    for (int yy = 0; yy < H; yy++) {
        int dy2 = (yy - y) * (yy - y);
        if (dy2 >= best) continue;
        #pragma unroll
        for (int w = 0; w < 3; w++) {
            uint32_t m = mtp[(yy + 2) * 5 + 1 + w];
            while (m) {
                int bp = __ffs(m) - 1; m &= m - 1;
                int dx = w * 32 + bp - x;
                best = min(best, dy2 + dx * dx);
            }
        }
    }
    return best;
}

__global__ void __launch_bounds__(NT, 1)
hd_all(const float* __restrict__ pred,
       const float* __restrict__ tgt,
       float* __restrict__ out)
{
    __shared__ uint32_t mtp[(H + 4) * 5];   // padded target mask
    __shared__ uint32_t sq[NWORDS];         // query mask words
    __shared__ int s_red[NWRP], s_any[NWRP];
    __shared__ int s_last;

    const int bx   = blockIdx.x;
    const int img  = bx >> 1;
    const int dir  = bx & 1;                // 0: q=pred,t=label ; 1: reverse
    const int tid  = threadIdx.x;
    const int lane = tid & 31;
    const int wrp  = tid >> 5;

    const float4* srcQ = (const float4*)(dir ? (tgt  + img * NPIX) : (pred + img * NPIX));
    const float4* srcT = (const float4*)(dir ? (pred + img * NPIX) : (tgt  + img * NPIX));

    // zero padded mask (interior rows overwritten below)
    if (tid < (H + 4) * 5) mtp[tid] = 0u;
    __syncthreads();        // mtp pad-zeroing must precede phase-A interior stores

    // ---- phase A: build BOTH masks locally (float4 -> nibble -> shfl-or) ----
    // one batch of 6 LDG.128; words assembled across 8-lane groups
    #pragma unroll
    for (int k = 0; k < 3; k++) {
        int i4 = tid + k * NT;
        float4 vq = srcQ[i4];
        float4 vt = srcT[i4];
        uint32_t nq = (vq.x >= TAU ? 1u : 0u) | (vq.y >= TAU ? 2u : 0u)
                    | (vq.z >= TAU ? 4u : 0u) | (vq.w >= TAU ? 8u : 0u);
        uint32_t nt = (vt.x >= TAU ? 1u : 0u) | (vt.y >= TAU ? 2u : 0u)
                    | (vt.z >= TAU ? 4u : 0u) | (vt.w >= TAU ? 8u : 0u);
        int shft = (i4 & 7) * 4;
        uint32_t wq = nq << shft;
        uint32_t wt = nt << shft;
        wq |= __shfl_xor_sync(0xFFFFFFFFu, wq, 1);
        wt |= __shfl_xor_sync(0xFFFFFFFFu, wt, 1);
        wq |= __shfl_xor_sync(0xFFFFFFFFu, wq, 2);
        wt |= __shfl_xor_sync(0xFFFFFFFFu, wt, 2);
        wq |= __shfl_xor_sync(0xFFFFFFFFu, wq, 4);
        wt |= __shfl_xor_sync(0xFFFFFFFFu, wt, 4);
        if ((lane & 7) == 0) {
            int w = i4 >> 3;                 // word index = y*3 + xw
            int y = w / 3, xw = w - y * 3;
            sq[w] = wq;
            mtp[(y + 2) * 5 + 1 + xw] = wt;
        }
    }
    __syncthreads();

    // ---- phase B: bitwise 5x5 dilation, one word (32 px) per thread ----
    int pmax = 0, tany = 0;
    if (tid < NWORDS) {
        const int y  = tid / 3;
        const int wc = tid - y * 3;
        uint32_t C[5], h1[5], h2[5];
        #pragma unroll
        for (int j = 0; j < 5; j++) {
            uint32_t l = mtp[(y + j) * 5 + wc];
            uint32_t c = mtp[(y + j) * 5 + wc + 1];
            uint32_t r = mtp[(y + j) * 5 + wc + 2];
            C[j]  = c;
            h1[j] = __funnelshift_l(l, c, 1) | __funnelshift_r(c, r, 1);
            h2[j] = __funnelshift_l(l, c, 2) | __funnelshift_r(c, r, 2);
        }
        uint32_t D0 = C[2];
        uint32_t D1 = D0 | h1[2] | C[1] | C[3];
        uint32_t D2 = D1 | h1[1] | h1[3];
        uint32_t D4 = D2 | h2[2] | C[0] | C[4];
        uint32_t D5 = D4 | h2[1] | h2[3] | h1[0] | h1[4];
        uint32_t D8 = D5 | h2[0] | h2[4];

        uint32_t q = sq[tid];
        tany = (D0 != 0u);
        pmax = (q & ~D5) ? 8 : (q & ~D4) ? 5 : (q & ~D2) ? 4
             : (q & ~D1) ? 2 : (q & ~D0) ? 1 : 0;

        uint32_t fb = q & ~D8;              // d2 >= 9: exact fallback (~never)
        while (fb) {
            int bp = __ffs(fb) - 1; fb &= fb - 1;
            pmax = max(pmax, full_search(mtp, wc * 32 + bp, y));
        }
    }

    // ---- block reduction (max d2, target-any) ----
    #pragma unroll
    for (int o = 16; o > 0; o >>= 1) {
        pmax = max(pmax, __shfl_xor_sync(0xFFFFFFFFu, pmax, o));
        tany |= __shfl_xor_sync(0xFFFFFFFFu, tany, o);
    }
    if (lane == 0) { s_red[wrp] = pmax; s_any[wrp] = tany; }
    __syncthreads();
    if (tid < 32) {
        int v = (tid < NWRP) ? s_red[tid] : 0;
        int a = (tid < NWRP) ? s_any[tid] : 0;
        #pragma unroll
        for (int o = 16; o > 0; o >>= 1) {
            v = max(v, __shfl_xor_sync(0xFFFFFFFFu, v, o));
            a |= __shfl_xor_sync(0xFFFFFFFFu, a, o);
        }
        if (tid == 0) {
            // sole owner of (img,dir): plain stores
            if (dir == 0) { g_maxAB[img] = v; g_anyL[img] = a; }
            else          { g_maxBA[img] = v; g_anyP[img] = a; }
            __threadfence();
            int old = atomicAdd(&g_done, 1);
            s_last = (old == NB - 1);
        }
    }
    __syncthreads();
    if (!s_last) return;
    __threadfence();

    // ---------------- finalize (exactly one block) ----------------
    __shared__ float hd[B];
    __shared__ int needs[B];    // 0 normal, 1 diam(pred), 2 diam(label)
    if (tid < B) {
        int aa = g_anyP[tid], bb = g_anyL[tid];
        if (aa && bb) {
            hd[tid] = sqrtf((float)max(g_maxAB[tid], g_maxBA[tid]));
            needs[tid] = 0;
        } else if (!aa && !bb) {
            hd[tid] = 0.0f;
            needs[tid] = 0;
        } else {
            needs[tid] = aa ? 1 : 2;
        }
    }
    if (tid == 0) g_done = 0;   // reset for next graph replay
    __syncthreads();

    // empty-set fallback: diameter (formal correctness; never runs on this data)
    __shared__ int s_diam;
    for (int im = 0; im < B; im++) {
        if (needs[im]) {
            const float* src2 = (needs[im] == 1) ? (pred + im * NPIX)
                                                 : (tgt  + im * NPIX);
            if (tid == 0) s_diam = 0;
            __syncthreads();
            int best = 0;
            for (int p = tid; p < NPIX; p += NT) {
                if (src2[p] >= TAU) {
                    int py = p / W, px = p - (p / W) * W;
                    for (int qq = 0; qq < NPIX; qq++) {
                        if (src2[qq] >= TAU) {
                            int dy = py - qq / W;
                            int dxx = px - (qq - (qq / W) * W);
                            best = max(best, dy * dy + dxx * dxx);
                        }
                    }
                }
            }
            atomicMax(&s_diam, best);
            __syncthreads();
            if (tid == 0) hd[im] = sqrtf((float)s_diam);
            __syncthreads();
        }
    }

    if (tid == 0) {
        float s = 0.0f;
        #pragma unroll
        for (int i = 0; i < B; i++) s += hd[i];
        out[0] = s * (1.0f / B);
    }
}

// ---------------------------------------------------------------------------
extern "C" void kernel_launch(void* const* d_in, const int* in_sizes, int n_in,
                              void* d_out, int out_size)
{
    const float* pred = (const float*)d_in[0];
    const float* tgt  = (const float*)d_in[1];
    float* out = (float*)d_out;

    hd_all<<<NB, NT>>>(pred, tgt, out);
}

// round 11
// speedup vs baseline: 1.1238x; 1.0782x over previous
#include <cuda_runtime.h>
#include <cuda_bf16.h>
#include <cstdint>
#include <math.h>

#define TAU 0.5f
#define B 16
#define H 96
#define W 96
#define NPIX (H * W)
#define NT 768            // 24 warps
#define NWRP (NT / 32)
#define NWORDS 288        // 96 rows x 3 words
#define PADW ((H + 4) * 5)
#define BIG 100000

// static device scratch (no allocation)
__device__ float g_hd[B];
__device__ int g_done = 0;

// exact search over padded target bitmask for one pixel (rare / far path)
__device__ __noinline__ int full_search(const uint32_t* mtp, int x, int y)
{
    int best = BIG;
    for (int yy = 0; yy < H; yy++) {
        int dy2 = (yy - y) * (yy - y);
        if (dy2 >= best) continue;
        #pragma unroll
        for (int w = 0; w < 3; w++) {
            uint32_t m = mtp[(yy + 2) * 5 + 1 + w];
            while (m) {
                int bp = __ffs(m) - 1; m &= m - 1;
                int dx = w * 32 + bp - x;
                best = min(best, dy2 + dx * dx);
            }
        }
    }
    return best;
}

// directed max-min d2: query words vs dilations of target mask
__device__ __forceinline__ void dilate_eval(const uint32_t* mtp, uint32_t q,
                                            int y, int wc, int& pmax, int& tany)
{
    uint32_t C[5], h1[5], h2[5];
    #pragma unroll
    for (int j = 0; j < 5; j++) {
        uint32_t l = mtp[(y + j) * 5 + wc];
        uint32_t c = mtp[(y + j) * 5 + wc + 1];
        uint32_t r = mtp[(y + j) * 5 + wc + 2];
        C[j]  = c;
        h1[j] = __funnelshift_l(l, c, 1) | __funnelshift_r(c, r, 1);
        h2[j] = __funnelshift_l(l, c, 2) | __funnelshift_r(c, r, 2);
    }
    uint32_t D0 = C[2];
    uint32_t D1 = D0 | h1[2] | C[1] | C[3];
    uint32_t D2 = D1 | h1[1] | h1[3];
    uint32_t D4 = D2 | h2[2] | C[0] | C[4];
    uint32_t D5 = D4 | h2[1] | h2[3] | h1[0] | h1[4];
    uint32_t D8 = D5 | h2[0] | h2[4];

    tany |= (D0 != 0u);
    int p = (q & ~D5) ? 8 : (q & ~D4) ? 5 : (q & ~D2) ? 4
          : (q & ~D1) ? 2 : (q & ~D0) ? 1 : 0;
    uint32_t fb = q & ~D8;               // d2 >= 9: exact fallback (~never)
    while (fb) {
        int bp = __ffs(fb) - 1; fb &= fb - 1;
        p = max(p, full_search(mtp, wc * 32 + bp, y));
    }
    pmax = max(pmax, p);
}

__global__ void __launch_bounds__(NT, 1)
hd_all(const float* __restrict__ pred,
       const float* __restrict__ tgt,
       float* __restrict__ out)
{
    __shared__ uint32_t mP[PADW];        // padded pred mask
    __shared__ uint32_t mL[PADW];        // padded label mask
    __shared__ int sAB[NWRP], sBA[NWRP], sANY[NWRP];
    __shared__ int s_last, s_needs, s_diam;

    const int img  = blockIdx.x;
    const int tid  = threadIdx.x;
    const int lane = tid & 31;
    const int wrp  = tid >> 5;

    const float4* srcP = (const float4*)(pred + img * NPIX);
    const float4* srcL = (const float4*)(tgt  + img * NPIX);

    // ---- issue ALL loads first (latency overlaps the zeroing below) ----
    float4 vp[3], vl[3];
    #pragma unroll
    for (int k = 0; k < 3; k++) {
        vp[k] = srcP[tid + k * NT];
        vl[k] = srcL[tid + k * NT];
    }

    // zero both padded arrays (interior overwritten after sync)
    if (tid < PADW) { mP[tid] = 0u; mL[tid] = 0u; }
    if (tid >= NT - (2 * PADW - NT) && tid < NT) {
        int i2 = tid + (2 * PADW - NT) - NT + NT; // fallthrough below
    }
    // second chunk of zeroing (PADW=500 -> need 1000 total slots, NT=768)
    {
        int z = tid + NT;
        if (z < 2 * PADW) {               // z in [768,1000): mL[268..500)
            mL[z - PADW] = 0u;
        }
    }
    __syncthreads();

    // ---- assemble both masks (nibble -> shfl-or across 8-lane groups) ----
    #pragma unroll
    for (int k = 0; k < 3; k++) {
        int i4 = tid + k * NT;
        uint32_t np = (vp[k].x >= TAU ? 1u : 0u) | (vp[k].y >= TAU ? 2u : 0u)
                    | (vp[k].z >= TAU ? 4u : 0u) | (vp[k].w >= TAU ? 8u : 0u);
        uint32_t nl = (vl[k].x >= TAU ? 1u : 0u) | (vl[k].y >= TAU ? 2u : 0u)
                    | (vl[k].z >= TAU ? 4u : 0u) | (vl[k].w >= TAU ? 8u : 0u);
        int shft = (i4 & 7) * 4;
        uint32_t wp = np << shft;
        uint32_t wl = nl << shft;
        wp |= __shfl_xor_sync(0xFFFFFFFFu, wp, 1);
        wl |= __shfl_xor_sync(0xFFFFFFFFu, wl, 1);
        wp |= __shfl_xor_sync(0xFFFFFFFFu, wp, 2);
        wl |= __shfl_xor_sync(0xFFFFFFFFu, wl, 2);
        wp |= __shfl_xor_sync(0xFFFFFFFFu, wp, 4);
        wl |= __shfl_xor_sync(0xFFFFFFFFu, wl, 4);
        if ((lane & 7) == 0) {
            int w = i4 >> 3;              // word index = y*3 + xw
            int y = w / 3, xw = w - y * 3;
            mP[(y + 2) * 5 + 1 + xw] = wp;
            mL[(y + 2) * 5 + 1 + xw] = wl;
        }
    }
    __syncthreads();

    // ---- both directions: bitwise 5x5 dilation, one word per thread ----
    int pmaxAB = 0, pmaxBA = 0, any = 0;   // any: bit0 = predAny, bit1 = labelAny
    if (tid < NWORDS) {
        const int y  = tid / 3;
        const int wc = tid - y * 3;
        uint32_t qP = mP[(y + 2) * 5 + 1 + wc];
        uint32_t qL = mL[(y + 2) * 5 + 1 + wc];
        int aL = 0, aP = 0;
        dilate_eval(mL, qP, y, wc, pmaxAB, aL);   // pred -> label
        dilate_eval(mP, qL, y, wc, pmaxBA, aP);   // label -> pred
        any = (aP ? 1 : 0) | (aL ? 2 : 0);
    }

    // ---- block reduction ----
    #pragma unroll
    for (int o = 16; o > 0; o >>= 1) {
        pmaxAB = max(pmaxAB, __shfl_xor_sync(0xFFFFFFFFu, pmaxAB, o));
        pmaxBA = max(pmaxBA, __shfl_xor_sync(0xFFFFFFFFu, pmaxBA, o));
        any   |= __shfl_xor_sync(0xFFFFFFFFu, any, o);
    }
    if (lane == 0) { sAB[wrp] = pmaxAB; sBA[wrp] = pmaxBA; sANY[wrp] = any; }
    __syncthreads();
    if (tid < 32) {
        int a = (tid < NWRP) ? sAB[tid] : 0;
        int b = (tid < NWRP) ? sBA[tid] : 0;
        int n = (tid < NWRP) ? sANY[tid] : 0;
        #pragma unroll
        for (int o = 16; o > 0; o >>= 1) {
            a = max(a, __shfl_xor_sync(0xFFFFFFFFu, a, o));
            b = max(b, __shfl_xor_sync(0xFFFFFFFFu, b, o));
            n |= __shfl_xor_sync(0xFFFFFFFFu, n, o);
        }
        if (tid == 0) {
            int aP = n & 1, aL = (n >> 1) & 1;
            if (aP && aL) {
                g_hd[img] = sqrtf((float)max(a, b));
                s_needs = 0;
            } else if (!aP && !aL) {
                g_hd[img] = 0.0f;
                s_needs = 0;
            } else {
                s_needs = aP ? 1 : 2;     // diameter of the nonempty set
            }
        }
    }
    __syncthreads();

    // ---- in-block empty-set fallback: diameter via bitmask (never runs here) ----
    if (s_needs) {
        const uint32_t* m = (s_needs == 1) ? mP : mL;
        if (tid == 0) s_diam = 0;
        __syncthreads();
        int best = 0;
        if (tid < NWORDS) {
            int y = tid / 3, wc = tid - y * 3;
            uint32_t bits = m[(y + 2) * 5 + 1 + wc];
            while (bits) {
                int bp = __ffs(bits) - 1; bits &= bits - 1;
                int x = wc * 32 + bp;
                for (int yy = 0; yy < H; yy++) {
                    int dy2 = (yy - y) * (yy - y);
                    #pragma unroll
                    for (int w = 0; w < 3; w++) {
                        uint32_t mm = m[(yy + 2) * 5 + 1 + w];
                        while (mm) {
                            int bq = __ffs(mm) - 1; mm &= mm - 1;
                            int dx = w * 32 + bq - x;
                            best = max(best, dy2 + dx * dx);
                        }
                    }
                }
            }
        }
        atomicMax(&s_diam, best);
        __syncthreads();
        if (tid == 0) g_hd[img] = sqrtf((float)s_diam);
    }

    // ---- tail: last block computes the mean (deterministic serial sum) ----
    if (tid == 0) {
        __threadfence();
        int old = atomicAdd(&g_done, 1);
        s_last = (old == B - 1);
    }
    __syncthreads();
    if (!s_last) return;
    if (tid == 0) {
        __threadfence();
        float s = 0.0f;
        #pragma unroll
        for (int i = 0; i < B; i++) s += g_hd[i];
        out[0] = s * (1.0f / B);
        g_done = 0;                       // reset for next graph replay
    }
}

// ---------------------------------------------------------------------------
extern "C" void kernel_launch(void* const* d_in, const int* in_sizes, int n_in,
                              void* d_out, int out_size)
{
    const float* pred = (const float*)d_in[0];
    const float* tgt  = (const float*)d_in[1];
    float* out = (float*)d_out;

    hd_all<<<B, NT>>>(pred, tgt, out);
}

// round 12
// speedup vs baseline: 1.2684x; 1.1287x over previous
#include <cuda_runtime.h>
#include <cuda_bf16.h>
#include <cstdint>
#include <math.h>

#define TAU 0.5f
#define B 16
#define H 96
#define W 96
#define NPIX (H * W)
#define NT 768            // 24 warps
#define NWRP (NT / 32)
#define NWORDS 288        // 96 rows x 3 words
#define PADW ((H + 4) * 5)
#define BIG 100000

// static device scratch (no allocation)
__device__ float g_sum = 0.0f;
__device__ int g_done = 0;

// exact search over padded target bitmask for one pixel (rare / far path)
__device__ __noinline__ int full_search(const uint32_t* mtp, int x, int y)
{
    int best = BIG;
    for (int yy = 0; yy < H; yy++) {
        int dy2 = (yy - y) * (yy - y);
        if (dy2 >= best) continue;
        #pragma unroll
        for (int w = 0; w < 3; w++) {
            uint32_t m = mtp[(yy + 2) * 5 + 1 + w];
            while (m) {
                int bp = __ffs(m) - 1; m &= m - 1;
                int dx = w * 32 + bp - x;
                best = min(best, dy2 + dx * dx);
            }
        }
    }
    return best;
}

// directed max-min d2 for one 32-px word vs dilations of target mask
__device__ __forceinline__ int dilate_eval(const uint32_t* mtp, uint32_t q,
                                           int y, int wc)
{
    uint32_t C[5], h1[5], h2[5];
    #pragma unroll
    for (int j = 0; j < 5; j++) {
        uint32_t l = mtp[(y + j) * 5 + wc];
        uint32_t c = mtp[(y + j) * 5 + wc + 1];
        uint32_t r = mtp[(y + j) * 5 + wc + 2];
        C[j]  = c;
        h1[j] = __funnelshift_l(l, c, 1) | __funnelshift_r(c, r, 1);
        h2[j] = __funnelshift_l(l, c, 2) | __funnelshift_r(c, r, 2);
    }
    uint32_t D0 = C[2];
    uint32_t D1 = D0 | h1[2] | C[1] | C[3];
    uint32_t D2 = D1 | h1[1] | h1[3];
    uint32_t D4 = D2 | h2[2] | C[0] | C[4];
    uint32_t D5 = D4 | h2[1] | h2[3] | h1[0] | h1[4];
    uint32_t D8 = D5 | h2[0] | h2[4];

    int p = (q & ~D5) ? 8 : (q & ~D4) ? 5 : (q & ~D2) ? 4
          : (q & ~D1) ? 2 : (q & ~D0) ? 1 : 0;
    uint32_t fb = q & ~D8;               // d2 >= 9: exact fallback (~never)
    while (fb) {
        int bp = __ffs(fb) - 1; fb &= fb - 1;
        p = max(p, full_search(mtp, wc * 32 + bp, y));
    }
    return p;
}

__global__ void __launch_bounds__(NT, 1)
hd_all(const float* __restrict__ pred,
       const float* __restrict__ tgt,
       float* __restrict__ out)
{
    __shared__ uint32_t mP[PADW];        // padded pred mask
    __shared__ uint32_t mL[PADW];        // padded label mask
    __shared__ int sAB[NWRP], sBA[NWRP], sANY[NWRP];
    __shared__ int s_last, s_needs, s_diam;

    const int img  = blockIdx.x;
    const int tid  = threadIdx.x;
    const int lane = tid & 31;
    const int wrp  = tid >> 5;

    const float4* srcP = (const float4*)(pred + img * NPIX);
    const float4* srcL = (const float4*)(tgt  + img * NPIX);

    // ---- issue ALL loads first (latency overlaps pad-zeroing below) ----
    float4 vp[3], vl[3];
    #pragma unroll
    for (int k = 0; k < 3; k++) {
        vp[k] = srcP[tid + k * NT];
        vl[k] = srcL[tid + k * NT];
    }

    // zero ONLY pad words (disjoint from interior writes -> no barrier needed)
    #pragma unroll
    for (int i = tid; i < 2 * PADW; i += NT) {
        int ii = (i < PADW) ? i : i - PADW;
        int r = ii / 5, c = ii - r * 5;
        if (r < 2 || r >= H + 2 || c == 0 || c == 4) {
            if (i < PADW) mP[ii] = 0u; else mL[ii] = 0u;
        }
    }

    // ---- phase A: assemble both masks (nibble -> shfl-or, 8-lane groups) ----
    #pragma unroll
    for (int k = 0; k < 3; k++) {
        int i4 = tid + k * NT;
        uint32_t np = (vp[k].x >= TAU ? 1u : 0u) | (vp[k].y >= TAU ? 2u : 0u)
                    | (vp[k].z >= TAU ? 4u : 0u) | (vp[k].w >= TAU ? 8u : 0u);
        uint32_t nl = (vl[k].x >= TAU ? 1u : 0u) | (vl[k].y >= TAU ? 2u : 0u)
                    | (vl[k].z >= TAU ? 4u : 0u) | (vl[k].w >= TAU ? 8u : 0u);
        int shft = (i4 & 7) * 4;
        uint32_t wp = np << shft;
        uint32_t wl = nl << shft;
        wp |= __shfl_xor_sync(0xFFFFFFFFu, wp, 1);
        wl |= __shfl_xor_sync(0xFFFFFFFFu, wl, 1);
        wp |= __shfl_xor_sync(0xFFFFFFFFu, wp, 2);
        wl |= __shfl_xor_sync(0xFFFFFFFFu, wl, 2);
        wp |= __shfl_xor_sync(0xFFFFFFFFu, wp, 4);
        wl |= __shfl_xor_sync(0xFFFFFFFFu, wl, 4);
        if ((lane & 7) == 0) {
            int w = i4 >> 3;              // word index = y*3 + xw
            int y = w / 3, xw = w - y * 3;
            mP[(y + 2) * 5 + 1 + xw] = wp;
            mL[(y + 2) * 5 + 1 + xw] = wl;
        }
    }
    __syncthreads();                      // the ONLY pre-compute barrier

    // ---- phase B: both directions, one word (32 px) per thread ----
    int pmaxAB = 0, pmaxBA = 0, any = 0;  // any: bit0=predAny, bit1=labelAny
    if (tid < NWORDS) {
        const int y  = tid / 3;
        const int wc = tid - y * 3;
        uint32_t qP = mP[(y + 2) * 5 + 1 + wc];
        uint32_t qL = mL[(y + 2) * 5 + 1 + wc];
        any = (qP ? 1 : 0) | (qL ? 2 : 0);
        pmaxAB = dilate_eval(mL, qP, y, wc);   // pred -> label
        pmaxBA = dilate_eval(mP, qL, y, wc);   // label -> pred
    }

    // ---- block reduction ----
    #pragma unroll
    for (int o = 16; o > 0; o >>= 1) {
        pmaxAB = max(pmaxAB, __shfl_xor_sync(0xFFFFFFFFu, pmaxAB, o));
        pmaxBA = max(pmaxBA, __shfl_xor_sync(0xFFFFFFFFu, pmaxBA, o));
        any   |= __shfl_xor_sync(0xFFFFFFFFu, any, o);
    }
    if (lane == 0) { sAB[wrp] = pmaxAB; sBA[wrp] = pmaxBA; sANY[wrp] = any; }
    __syncthreads();

    float myhd = 0.0f;                    // meaningful on tid 0 only
    if (tid < 32) {
        int a = (tid < NWRP) ? sAB[tid] : 0;
        int b = (tid < NWRP) ? sBA[tid] : 0;
        int n = (tid < NWRP) ? sANY[tid] : 0;
        #pragma unroll
        for (int o = 16; o > 0; o >>= 1) {
            a = max(a, __shfl_xor_sync(0xFFFFFFFFu, a, o));
            b = max(b, __shfl_xor_sync(0xFFFFFFFFu, b, o));
            n |= __shfl_xor_sync(0xFFFFFFFFu, n, o);
        }
        if (tid == 0) {
            int aP = n & 1, aL = (n >> 1) & 1;
            if (aP && aL)      { myhd = sqrtf((float)max(a, b)); s_needs = 0; }
            else if (!aP && !aL) { myhd = 0.0f; s_needs = 0; }
            else               { s_needs = aP ? 1 : 2; }   // diameter fallback
        }
    }
    __syncthreads();

    // ---- in-block empty-set fallback: diameter via bitmask (never runs here) ----
    if (s_needs) {
        const uint32_t* m = (s_needs == 1) ? mP : mL;
        if (tid == 0) s_diam = 0;
        __syncthreads();
        int best = 0;
        if (tid < NWORDS) {
            int y = tid / 3, wc = tid - y * 3;
            uint32_t bits = m[(y + 2) * 5 + 1 + wc];
            while (bits) {
                int bp = __ffs(bits) - 1; bits &= bits - 1;
                int x = wc * 32 + bp;
                for (int yy = 0; yy < H; yy++) {
                    int dy2 = (yy - y) * (yy - y);
                    #pragma unroll
                    for (int w = 0; w < 3; w++) {
                        uint32_t mm = m[(yy + 2) * 5 + 1 + w];
                        while (mm) {
                            int bq = __ffs(mm) - 1; mm &= mm - 1;
                            int dx = w * 32 + bq - x;
                            best = max(best, dy2 + dx * dx);
                        }
                    }
                }
            }
        }
        atomicMax(&s_diam, best);
        __syncthreads();
        if (tid == 0) myhd = sqrtf((float)s_diam);
    }

    // ---- tail: accumulate mean; last block writes the scalar ----
    if (tid == 0) {
        atomicAdd(&g_sum, myhd);
        __threadfence();
        int old = atomicAdd(&g_done, 1);
        s_last = (old == B - 1);
    }
    __syncthreads();
    if (!s_last) return;
    if (tid == 0) {
        __threadfence();
        float s = *(volatile float*)&g_sum;
        out[0] = s * (1.0f / B);
        g_sum = 0.0f;                     // reset for next graph replay
        g_done = 0;
    }
}

// ---------------------------------------------------------------------------
extern "C" void kernel_launch(void* const* d_in, const int* in_sizes, int n_in,
                              void* d_out, int out_size)
{
    const float* pred = (const float*)d_in[0];
    const float* tgt  = (const float*)d_in[1];
    float* out = (float*)d_out;

    hd_all<<<B, NT>>>(pred, tgt, out);
}